// round 15
// baseline (speedup 1.0000x reference)
#include <cuda_runtime.h>
#include <cstdint>

#define DIMZ 96
#define OUT_ROW 4753            // 1 + 96 + 96*97/2
#define G 4                     // rows per CTA
#define TPB 256
#define NVEC 4753               // float4s per CTA superblock (G*OUT_ROW/4)
#define CST 392                 // rotated-copy stride in words (mult of 8)
#define NPAIRIT 9               // paired iterations: 9*512 = 4608 v's
#define VTAIL (NPAIRIT * 2 * TPB)  // 4608
#define NSEGTOT (G * 97)        // 388

// All tables are pure compile-time constants: generated by a constexpr pass.
//
// zext = [1, z_row] concatenated over the CTA's 4 rows (388 entries).
// Element order per row: segment i'=0 is (a=base, b=base..base+96) -> const +
// linear terms; segments i'=1..96 are (a=base+i', b=base+i'..base+96) -> quads.
// Every segment starts at b==a, and consecutive segments (incl. row
// transitions) have a' = a+1 -> the crossing pattern decode "a+=1, b=a" holds.
//
// Scalar desc: bits 0..12 = byte offset of the zj LDS.128 (rotated smem copy
// folded in), bits 13..23 = byte offset of zi.
// Crossing entry: x = v | (pbits<<13), y = a0 | (b0<<10).

struct Tables {
    uint32_t ab[NVEC];
    uint2    ab2[NPAIRIT * TPB];
    uint2    cross[512];
    int      ncross;
};

constexpr uint32_t make_desc_ab(int a0, int b0) {
    int c = b0 & 3;
    return (uint32_t)(4 * (c * CST + (b0 - c))) | ((uint32_t)(4 * a0) << 13);
}

constexpr Tables gen_tables() {
    Tables T{};
    int l = 0;
    int a0 = 0, b0 = 0, pbits = 0, preva = 0;
    for (int r = 0; r < G; r++) {
        int base = r * 97;
        for (int seg = 0; seg <= 96; seg++) {
            int a = base + seg;
            int bstart = (seg == 0) ? base : base + seg;
            for (int b = bstart; b <= base + 96; b++) {
                int e = l & 3;
                if (e == 0) { a0 = a; b0 = b; pbits = 0; preva = a; }
                else {
                    if (a != preva) pbits |= (1 << (e - 1));
                    preva = a;
                }
                if (e == 3) {
                    int v = l >> 2;
                    T.ab[v] = make_desc_ab(a0, b0);
                    if (pbits != 0) {
                        T.cross[T.ncross].x = (uint32_t)v | ((uint32_t)pbits << 13);
                        T.cross[T.ncross].y = (uint32_t)a0 | ((uint32_t)b0 << 10);
                        T.ncross++;
                    }
                }
                l++;
            }
        }
    }
    // v = 4752 has no e==3 slot?  4753*4 = 19012 elements; l runs 0..19011,
    // last e==3 at l=19011 -> v=4752 covered.  (19012 % 4 == 0.)
    // paired table
    for (int m = 0; m < NPAIRIT; m++) {
        for (int t = 0; t < TPB; t++) {
            int v0 = m * 2 * TPB + t;
            T.ab2[m * TPB + t].x = T.ab[v0];
            T.ab2[m * TPB + t].y = T.ab[v0 + TPB];
        }
    }
    return T;
}

__device__ constexpr Tables g_T = gen_tables();

__global__ __launch_bounds__(TPB) void poly_kernel(const float* __restrict__ z,
                                                   float* __restrict__ out) {
    // 4 rotated copies of zext: zsh[c*CST + x] = zext(x + c), zero-padded.
    // zext(y): y%97==0 -> 1.0, else z_row[y%97 - 1], rows concatenated.
    __shared__ float zsh[4 * CST];

    const int tid = threadIdx.x;
    const float* zr = z + (size_t)blockIdx.x * (G * DIMZ);

    for (int w = tid; w < 4 * CST; w += TPB) {
        int c = w / CST;
        int x = w - c * CST;
        int y = x + c;
        float val = 0.0f;
        if (y < NSEGTOT) {
            int row = y / 97, pos = y - row * 97;
            val = (pos == 0) ? 1.0f : zr[row * DIMZ + pos - 1];
        }
        zsh[w] = val;
    }
    __syncthreads();

    float4* o4 = (float4*)(out + (size_t)blockIdx.x * (G * OUT_ROW));
    const char* zb8 = (const char*)zsh;

    // ---- main loop: paired descriptors, branch-free, fully unconditional.
    // Crossing slots get garbage; fixed up after the barrier. ----
    #pragma unroll 4
    for (int m = 0; m < NPAIRIT; m++) {
        const uint2 dd = __ldg(&g_T.ab2[m * TPB + tid]);
        const int v0 = m * 2 * TPB + tid;

        const float4 zj0 = *(const float4*)(zb8 + (dd.x & 0x1FFFu));
        const float  zi0 = *(const float*)(zb8 + (dd.x >> 13));
        const float4 zj1 = *(const float4*)(zb8 + (dd.y & 0x1FFFu));
        const float  zi1 = *(const float*)(zb8 + (dd.y >> 13));

        float4 r0, r1;
        r0.x = zi0 * zj0.x; r0.y = zi0 * zj0.y;
        r0.z = zi0 * zj0.z; r0.w = zi0 * zj0.w;
        r1.x = zi1 * zj1.x; r1.y = zi1 * zj1.y;
        r1.z = zi1 * zj1.z; r1.w = zi1 * zj1.w;

        __stcs(&o4[v0], r0);
        __stcs(&o4[v0 + TPB], r1);
    }

    // ---- scalar tail: v in [4608, 4753) ----
    for (int v = VTAIL + tid; v < NVEC; v += TPB) {
        const uint32_t d = __ldg(&g_T.ab[v]);
        const float4 zj = *(const float4*)(zb8 + (d & 0x1FFFu));
        const float  zi = *(const float*)(zb8 + (d >> 13));
        float4 res;
        res.x = zi * zj.x;
        res.y = zi * zj.y;
        res.z = zi * zj.z;
        res.w = zi * zj.w;
        __stcs(&o4[v], res);
    }

    // Barrier orders all main-loop stores before the fixup overwrites.
    __syncthreads();

    // ---- fixup: overwrite the ~291 segment-crossing float4s ----
    const int nc = g_T.ncross;
    for (int s = tid; s < nc; s += TPB) {
        const uint2 e = __ldg(&g_T.cross[s]);
        const int v = e.x & 0x1FFF;
        const uint32_t p = e.x >> 13;
        int a = e.y & 1023;
        int b = (e.y >> 10) & 1023;
        float4 res;
        res.x = zsh[a] * zsh[b];
        a += (p & 1u);        b = (p & 1u) ? a : (b + 1);
        res.y = zsh[a] * zsh[b];
        a += ((p >> 1) & 1u); b = ((p >> 1) & 1u) ? a : (b + 1);
        res.z = zsh[a] * zsh[b];
        a += ((p >> 2) & 1u); b = ((p >> 2) & 1u) ? a : (b + 1);
        res.w = zsh[a] * zsh[b];
        __stcs(&o4[v], res);
    }
}

extern "C" void kernel_launch(void* const* d_in, const int* in_sizes, int n_in,
                              void* d_out, int out_size) {
    const float* z = (const float*)d_in[0];
    float* out = (float*)d_out;
    const int B = in_sizes[0] / DIMZ;   // 32768, divisible by G=4

    poly_kernel<<<B / G, TPB>>>(z, out);
}

// round 16
// speedup vs baseline: 1.6078x; 1.6078x over previous
#include <cuda_runtime.h>
#include <cstdint>

#define DIMZ 96
#define OUT_ROW 4753            // 1 + 96 + 96*97/2
#define G 4                     // rows per CTA
#define TPB 256
#define NVEC 4753               // float4s per CTA superblock (G*OUT_ROW/4)
#define CST 392                 // rotated-copy stride in words (mult of 8)
#define NPAIRIT 9               // paired iterations: 9*512 = 4608 v's
#define VTAIL (NPAIRIT * 2 * TPB)  // 4608
#define NSEGTOT (G * 97)        // 388

// All tables are compile-time generated, but placed in GLOBAL memory
// (__device__ const, NOT constexpr: constexpr device vars land in the
// constant bank, where per-lane divergent access serializes -- R15 lesson).

struct Tables {
    uint32_t ab[NVEC];
    uint2    ab2[NPAIRIT * TPB];
    uint2    cross[512];
    int      ncross;
};

constexpr uint32_t make_desc_ab(int a0, int b0) {
    int c = b0 & 3;
    return (uint32_t)(4 * (c * CST + (b0 - c))) | ((uint32_t)(4 * a0) << 13);
}

constexpr Tables gen_tables() {
    Tables T{};
    int l = 0;
    int a0 = 0, b0 = 0, pbits = 0, preva = 0;
    for (int r = 0; r < G; r++) {
        int base = r * 97;
        for (int seg = 0; seg <= 96; seg++) {
            int a = base + seg;
            int bstart = (seg == 0) ? base : base + seg;
            for (int b = bstart; b <= base + 96; b++) {
                int e = l & 3;
                if (e == 0) { a0 = a; b0 = b; pbits = 0; preva = a; }
                else {
                    if (a != preva) pbits |= (1 << (e - 1));
                    preva = a;
                }
                if (e == 3) {
                    int v = l >> 2;
                    T.ab[v] = make_desc_ab(a0, b0);
                    if (pbits != 0) {
                        T.cross[T.ncross].x = (uint32_t)v | ((uint32_t)pbits << 13);
                        T.cross[T.ncross].y = (uint32_t)a0 | ((uint32_t)b0 << 10);
                        T.ncross++;
                    }
                }
                l++;
            }
        }
    }
    for (int m = 0; m < NPAIRIT; m++) {
        for (int t = 0; t < TPB; t++) {
            int v0 = m * 2 * TPB + t;
            T.ab2[m * TPB + t].x = T.ab[v0];
            T.ab2[m * TPB + t].y = T.ab[v0 + TPB];
        }
    }
    return T;
}

// Global-memory placement; statically initialized at module load.
__device__ const Tables g_T = gen_tables();

__global__ __launch_bounds__(TPB) void poly_kernel(const float* __restrict__ z,
                                                   float* __restrict__ out) {
    // 4 rotated copies of zext: zsh[c*CST + x] = zext(x + c), zero-padded.
    // zext(y): y%97==0 -> 1.0, else z_row[y%97 - 1], rows concatenated.
    __shared__ float zsh[4 * CST];

    const int tid = threadIdx.x;
    const float* zr = z + (size_t)blockIdx.x * (G * DIMZ);

    for (int w = tid; w < 4 * CST; w += TPB) {
        int c = w / CST;
        int x = w - c * CST;
        int y = x + c;
        float val = 0.0f;
        if (y < NSEGTOT) {
            int row = y / 97, pos = y - row * 97;
            val = (pos == 0) ? 1.0f : zr[row * DIMZ + pos - 1];
        }
        zsh[w] = val;
    }
    __syncthreads();

    float4* o4 = (float4*)(out + (size_t)blockIdx.x * (G * OUT_ROW));
    const char* zb8 = (const char*)zsh;

    // ---- main loop: paired descriptors, branch-free, fully unconditional.
    // Crossing slots get garbage; fixed up after the barrier. ----
    #pragma unroll 4
    for (int m = 0; m < NPAIRIT; m++) {
        const uint2 dd = __ldg(&g_T.ab2[m * TPB + tid]);
        const int v0 = m * 2 * TPB + tid;

        const float4 zj0 = *(const float4*)(zb8 + (dd.x & 0x1FFFu));
        const float  zi0 = *(const float*)(zb8 + (dd.x >> 13));
        const float4 zj1 = *(const float4*)(zb8 + (dd.y & 0x1FFFu));
        const float  zi1 = *(const float*)(zb8 + (dd.y >> 13));

        float4 r0, r1;
        r0.x = zi0 * zj0.x; r0.y = zi0 * zj0.y;
        r0.z = zi0 * zj0.z; r0.w = zi0 * zj0.w;
        r1.x = zi1 * zj1.x; r1.y = zi1 * zj1.y;
        r1.z = zi1 * zj1.z; r1.w = zi1 * zj1.w;

        __stcs(&o4[v0], r0);
        __stcs(&o4[v0 + TPB], r1);
    }

    // ---- scalar tail: v in [4608, 4753) ----
    for (int v = VTAIL + tid; v < NVEC; v += TPB) {
        const uint32_t d = __ldg(&g_T.ab[v]);
        const float4 zj = *(const float4*)(zb8 + (d & 0x1FFFu));
        const float  zi = *(const float*)(zb8 + (d >> 13));
        float4 res;
        res.x = zi * zj.x;
        res.y = zi * zj.y;
        res.z = zi * zj.z;
        res.w = zi * zj.w;
        __stcs(&o4[v], res);
    }

    // Barrier orders all main-loop stores before the fixup overwrites.
    __syncthreads();

    // ---- fixup: overwrite the ~291 segment-crossing float4s ----
    const int nc = g_T.ncross;
    for (int s = tid; s < nc; s += TPB) {
        const uint2 e = __ldg(&g_T.cross[s]);
        const int v = e.x & 0x1FFF;
        const uint32_t p = e.x >> 13;
        int a = e.y & 1023;
        int b = (e.y >> 10) & 1023;
        float4 res;
        res.x = zsh[a] * zsh[b];
        a += (p & 1u);        b = (p & 1u) ? a : (b + 1);
        res.y = zsh[a] * zsh[b];
        a += ((p >> 1) & 1u); b = ((p >> 1) & 1u) ? a : (b + 1);
        res.z = zsh[a] * zsh[b];
        a += ((p >> 2) & 1u); b = ((p >> 2) & 1u) ? a : (b + 1);
        res.w = zsh[a] * zsh[b];
        __stcs(&o4[v], res);
    }
}

extern "C" void kernel_launch(void* const* d_in, const int* in_sizes, int n_in,
                              void* d_out, int out_size) {
    const float* z = (const float*)d_in[0];
    float* out = (float*)d_out;
    const int B = in_sizes[0] / DIMZ;   // 32768, divisible by G=4

    poly_kernel<<<B / G, TPB>>>(z, out);
}

// round 17
// speedup vs baseline: 1.6549x; 1.0293x over previous
#include <cuda_runtime.h>
#include <cstdint>

#define DIMZ 96
#define OUT_ROW 4753            // 1 + 96 + 96*97/2
#define G 4                     // rows per CTA
#define TPB 256
#define NVEC 4753               // float4s per CTA superblock (G*OUT_ROW/4)
#define CST 392                 // rotated-copy stride in words (mult of 8)
#define NPAIRIT 9               // paired iterations: 9*512 = 4608 v's
#define VTAIL (NPAIRIT * 2 * TPB)  // 4608
#define NSEGTOT (G * 97)        // 388

// All tables are compile-time generated, placed in GLOBAL memory
// (__device__ const, NOT constexpr: constexpr device vars land in the
// constant bank, where per-lane divergent access serializes -- R15 lesson).

struct Tables {
    uint32_t ab[NVEC];
    uint2    ab2[NPAIRIT * TPB];
    uint2    cross[512];
    int      ncross;
};

constexpr uint32_t make_desc_ab(int a0, int b0) {
    int c = b0 & 3;
    return (uint32_t)(4 * (c * CST + (b0 - c))) | ((uint32_t)(4 * a0) << 13);
}

constexpr Tables gen_tables() {
    Tables T{};
    int l = 0;
    int a0 = 0, b0 = 0, pbits = 0, preva = 0;
    for (int r = 0; r < G; r++) {
        int base = r * 97;
        for (int seg = 0; seg <= 96; seg++) {
            int a = base + seg;
            int bstart = (seg == 0) ? base : base + seg;
            for (int b = bstart; b <= base + 96; b++) {
                int e = l & 3;
                if (e == 0) { a0 = a; b0 = b; pbits = 0; preva = a; }
                else {
                    if (a != preva) pbits |= (1 << (e - 1));
                    preva = a;
                }
                if (e == 3) {
                    int v = l >> 2;
                    T.ab[v] = make_desc_ab(a0, b0);
                    if (pbits != 0) {
                        T.cross[T.ncross].x = (uint32_t)v | ((uint32_t)pbits << 13);
                        T.cross[T.ncross].y = (uint32_t)a0 | ((uint32_t)b0 << 10);
                        T.ncross++;
                    }
                }
                l++;
            }
        }
    }
    for (int m = 0; m < NPAIRIT; m++) {
        for (int t = 0; t < TPB; t++) {
            int v0 = m * 2 * TPB + t;
            T.ab2[m * TPB + t].x = T.ab[v0];
            T.ab2[m * TPB + t].y = T.ab[v0 + TPB];
        }
    }
    return T;
}

// Global-memory placement; statically initialized at module load.
__device__ const Tables g_T = gen_tables();

__global__ __launch_bounds__(TPB) void poly_kernel(const float* __restrict__ z,
                                                   float* __restrict__ out) {
    // 4 rotated copies of zext: zsh[c*CST + x] = zext(x + c), zero-padded.
    // zext(y): y%97==0 -> 1.0, else z_row[y%97 - 1], rows concatenated.
    __shared__ float zsh[4 * CST];

    const int tid = threadIdx.x;
    const float* zr = z + (size_t)blockIdx.x * (G * DIMZ);

    for (int w = tid; w < 4 * CST; w += TPB) {
        int c = w / CST;
        int x = w - c * CST;
        int y = x + c;
        float val = 0.0f;
        if (y < NSEGTOT) {
            int row = y / 97, pos = y - row * 97;
            val = (pos == 0) ? 1.0f : zr[row * DIMZ + pos - 1];
        }
        zsh[w] = val;
    }
    __syncthreads();

    float4* o4 = (float4*)(out + (size_t)blockIdx.x * (G * OUT_ROW));
    const char* zb8 = (const char*)zsh;

    // ---- main loop: paired descriptors, branch-free, fully unconditional,
    // FULLY unrolled so ptxas can front-batch all 9 descriptor LDG.64s.
    // Crossing slots get garbage; fixed up after the barrier. ----
    #pragma unroll
    for (int m = 0; m < NPAIRIT; m++) {
        const uint2 dd = __ldg(&g_T.ab2[m * TPB + tid]);
        const int v0 = m * 2 * TPB + tid;

        const float4 zj0 = *(const float4*)(zb8 + (dd.x & 0x1FFFu));
        const float  zi0 = *(const float*)(zb8 + (dd.x >> 13));
        const float4 zj1 = *(const float4*)(zb8 + (dd.y & 0x1FFFu));
        const float  zi1 = *(const float*)(zb8 + (dd.y >> 13));

        float4 r0, r1;
        r0.x = zi0 * zj0.x; r0.y = zi0 * zj0.y;
        r0.z = zi0 * zj0.z; r0.w = zi0 * zj0.w;
        r1.x = zi1 * zj1.x; r1.y = zi1 * zj1.y;
        r1.z = zi1 * zj1.z; r1.w = zi1 * zj1.w;

        __stcs(&o4[v0], r0);
        __stcs(&o4[v0 + TPB], r1);
    }

    // ---- scalar tail: v in [4608, 4753) ----
    for (int v = VTAIL + tid; v < NVEC; v += TPB) {
        const uint32_t d = __ldg(&g_T.ab[v]);
        const float4 zj = *(const float4*)(zb8 + (d & 0x1FFFu));
        const float  zi = *(const float*)(zb8 + (d >> 13));
        float4 res;
        res.x = zi * zj.x;
        res.y = zi * zj.y;
        res.z = zi * zj.z;
        res.w = zi * zj.w;
        __stcs(&o4[v], res);
    }

    // Barrier orders all main-loop stores before the fixup overwrites.
    __syncthreads();

    // ---- fixup: overwrite the ~291 segment-crossing float4s ----
    const int nc = g_T.ncross;
    for (int s = tid; s < nc; s += TPB) {
        const uint2 e = __ldg(&g_T.cross[s]);
        const int v = e.x & 0x1FFF;
        const uint32_t p = e.x >> 13;
        int a = e.y & 1023;
        int b = (e.y >> 10) & 1023;
        float4 res;
        res.x = zsh[a] * zsh[b];
        a += (p & 1u);        b = (p & 1u) ? a : (b + 1);
        res.y = zsh[a] * zsh[b];
        a += ((p >> 1) & 1u); b = ((p >> 1) & 1u) ? a : (b + 1);
        res.z = zsh[a] * zsh[b];
        a += ((p >> 2) & 1u); b = ((p >> 2) & 1u) ? a : (b + 1);
        res.w = zsh[a] * zsh[b];
        __stcs(&o4[v], res);
    }
}

extern "C" void kernel_launch(void* const* d_in, const int* in_sizes, int n_in,
                              void* d_out, int out_size) {
    const float* z = (const float*)d_in[0];
    float* out = (float*)d_out;
    const int B = in_sizes[0] / DIMZ;   // 32768, divisible by G=4

    poly_kernel<<<B / G, TPB>>>(z, out);
}